// round 14
// baseline (speedup 1.0000x reference)
#include <cuda_runtime.h>
#include <cuda_fp16.h>
#include <cuda_bf16.h>
#include <cstdint>

#define B_  64
#define T_  1024
#define A_  128
#define F_  1024
#define KC_ 31
#define DQ_ 1024
#define DV_ 512
#define J_  62
#define NCS 8           // kS t-chunks
#define TCS 128         // t per chunk
#define NTT 8           // t-tiles of 128
#define NCH 8           // k-chunks of 64
#define CHK 8192        // elems per bf16 image chunk (128 x 64)

// ---- scratch (device globals) ----
__device__ __half g_vh[B_*T_*A_];
__device__ float g_q [B_*A_];
__device__ float g_qp[256*A_];
__device__ float g_e [B_*T_];
__device__ float g_Sp[B_*NCS*J_*A_];
__device__ __align__(16) __nv_bfloat16 gBimg[2][NCH][CHK];  // Wm^T   (row=a)
__device__ __align__(16) __nv_bfloat16 gCimg[2][NTT][CHK];  // Wconv^T(row=t_local)
__device__ __align__(16) __nv_bfloat16 gSimg[2][B_ ][CHK];  // S^T    (row=a)
// value bf16 hi/lo images: [(b*T+t)*8 + chunk][64]
__device__ __align__(16) __nv_bfloat16 gVimg[2][(size_t)B_*T_*DV_];

__device__ __forceinline__ float ftanh(float x) {
    float e = __expf(2.0f * x);
    return 1.0f - __fdividef(2.0f, e + 1.0f);
}

__device__ __forceinline__ void split8(const float* x, uint4& hi, uint4& lo) {
    unsigned hw[4], lw[4];
    #pragma unroll
    for (int p = 0; p < 4; p++) {
        __nv_bfloat162 h = __floats2bfloat162_rn(x[2*p], x[2*p+1]);
        float r0 = x[2*p]   - __low2float(h);
        float r1 = x[2*p+1] - __high2float(h);
        __nv_bfloat162 l = __floats2bfloat162_rn(r0, r1);
        hw[p] = *reinterpret_cast<unsigned*>(&h);
        lw[p] = *reinterpret_cast<unsigned*>(&l);
    }
    hi = make_uint4(hw[0], hw[1], hw[2], hw[3]);
    lo = make_uint4(lw[0], lw[1], lw[2], lw[3]);
}

#define CP16(dst_u32, src_ptr) \
    asm volatile("cp.async.ca.shared.global [%0], [%1], 16;" \
                 :: "r"(dst_u32), "l"(src_ptr) : "memory")
#define CP_COMMIT() asm volatile("cp.async.commit_group;" ::: "memory")
#define CP_WAIT0()  asm volatile("cp.async.wait_group 0;" ::: "memory")

#define LDSM4(r, addr) \
    asm volatile("ldmatrix.sync.aligned.m8n8.x4.shared.b16 {%0,%1,%2,%3}, [%4];" \
        : "=r"((r)[0]), "=r"((r)[1]), "=r"((r)[2]), "=r"((r)[3]) : "r"(addr))

__device__ __forceinline__ void mma4(float* c, const uint32_t* a,
                                     uint32_t b0, uint32_t b1) {
    asm volatile(
        "mma.sync.aligned.m16n8k16.row.col.f32.bf16.bf16.f32 "
        "{%0,%1,%2,%3},{%4,%5,%6,%7},{%8,%9},{%0,%1,%2,%3};"
        : "+f"(c[0]), "+f"(c[1]), "+f"(c[2]), "+f"(c[3])
        : "r"(a[0]), "r"(a[1]), "r"(a[2]), "r"(a[3]), "r"(b0), "r"(b1));
}

// ==== stage 1: value-conv | kq-partials | prepB | prepC | kS (fused) ====
// [0,1024):      value fp32 -> bf16 hi/lo images (b = blk>>4, 64-row segment)
// [1024,1280):   kq partial
// [1280,1288):   prepB
// [1288,1296):   prepC
// [1296,1808):   kS
#define S1_CV   1024
#define S1_KQ   (S1_CV + 256)
#define S1_PB   (S1_KQ + NCH)
#define S1_PC   (S1_PB + NTT)
#define S1_TOT  (S1_PC + B_*NCS)

__global__ __launch_bounds__(128) void kstage1(const float* __restrict__ value,
                                               const float* __restrict__ query,
                                               const float* __restrict__ Wq,
                                               const float* __restrict__ Wm,
                                               const float* __restrict__ Wconv,
                                               const float* __restrict__ aw,
                                               const float* __restrict__ Wloc) {
    int blk = blockIdx.x;
    int tid = threadIdx.x;

    if (blk < S1_CV) {                     // ---- value conversion ----
        int b   = blk >> 4;
        int seg = blk & 15;
        int t   = seg*64 + (tid >> 1);
        int kh  = tid & 1;                 // halves of k (256 floats each)
        const float* src = value + ((size_t)b*T_ + t)*DV_ + kh*256;
        #pragma unroll 1
        for (int c4 = 0; c4 < 4; c4++) {
            int c = kh*4 + c4;
            size_t obase = (((size_t)b*T_ + t)*8 + c)*64;
            #pragma unroll
            for (int g = 0; g < 8; g++) {
                float x[8];
                float4 f0 = *reinterpret_cast<const float4*>(src + c4*64 + g*8);
                float4 f1 = *reinterpret_cast<const float4*>(src + c4*64 + g*8 + 4);
                x[0]=f0.x; x[1]=f0.y; x[2]=f0.z; x[3]=f0.w;
                x[4]=f1.x; x[5]=f1.y; x[6]=f1.z; x[7]=f1.w;
                uint4 hi, lo;
                split8(x, hi, lo);
                *reinterpret_cast<uint4*>(&gVimg[0][obase + g*8]) = hi;
                *reinterpret_cast<uint4*>(&gVimg[1][obase + g*8]) = lo;
            }
        }
    } else if (blk < S1_KQ) {              // ---- kq partial ----
        int i = blk - S1_CV;
        int b = i >> 2, qq = i & 3;
        __shared__ float qs[256];
        qs[tid]       = query[b*DQ_ + qq*256 + tid];
        qs[tid + 128] = query[b*DQ_ + qq*256 + 128 + tid];
        __syncthreads();
        float acc = 0.0f;
        #pragma unroll 8
        for (int d = 0; d < 256; d++)
            acc = fmaf(qs[d], Wq[(size_t)(qq*256 + d)*A_ + tid], acc);
        g_qp[i*A_ + tid] = acc;
    } else if (blk < S1_PB) {              // ---- prepB ----
        int c = blk - S1_KQ;
        #pragma unroll 1
        for (int k8 = 0; k8 < 8; k8++) {
            float x[8];
            #pragma unroll
            for (int i = 0; i < 8; i++)
                x[i] = Wm[(size_t)(c*64 + k8*8 + i)*A_ + tid];
            uint4 hi, lo;
            split8(x, hi, lo);
            *reinterpret_cast<uint4*>(&gBimg[0][c][tid*64 + k8*8]) = hi;
            *reinterpret_cast<uint4*>(&gBimg[1][c][tid*64 + k8*8]) = lo;
        }
    } else if (blk < S1_PC) {              // ---- prepC ----
        int tt = blk - S1_PB;
        #pragma unroll 1
        for (int k8 = 0; k8 < 8; k8++) {
            float x[8];
            #pragma unroll
            for (int i = 0; i < 8; i++) {
                int j = k8*8 + i;
                x[i] = (j < J_) ? Wconv[(size_t)j*F_ + tt*128 + tid] : 0.0f;
            }
            uint4 hi, lo;
            split8(x, hi, lo);
            *reinterpret_cast<uint4*>(&gCimg[0][tt][tid*64 + k8*8]) = hi;
            *reinterpret_cast<uint4*>(&gCimg[1][tt][tid*64 + k8*8]) = lo;
        }
    } else {                               // ---- kS ----
        int i  = blk - S1_PC;
        int b  = i >> 3;
        int ch = i & 7;
        int t0 = ch * TCS;

        __shared__ float2 awm2[TCS + KC_ - 1];
        for (int idx = tid; idx < TCS + KC_ - 1; idx += 128) {
            int t = t0 + idx - 15;
            float2 v = make_float2(0.0f, 0.0f);
            if (t >= 0 && t < T_) {
                v.x = aw[(b*T_ + t)*2 + 0];
                v.y = aw[(b*T_ + t)*2 + 1];
            }
            awm2[idx] = v;
        }
        __syncthreads();

        unsigned long long acc2[KC_];
        #pragma unroll
        for (int k = 0; k < KC_; k++) acc2[k] = 0ull;

        #pragma unroll 1
        for (int tl = 0; tl < TCS; tl++) {
            float w = Wloc[(size_t)(t0 + tl)*A_ + tid];
            unsigned long long wd;
            asm("mov.b64 %0, {%1,%1};" : "=l"(wd) : "f"(w));
            #pragma unroll
            for (int k = 0; k < KC_; k++) {
                unsigned long long bv = *reinterpret_cast<const unsigned long long*>(&awm2[tl + k]);
                asm("fma.rn.f32x2 %0, %1, %2, %0;" : "+l"(acc2[k]) : "l"(wd), "l"(bv));
            }
        }
        float* dst = &g_Sp[((size_t)(b*NCS + ch)*J_)*A_ + tid];
        #pragma unroll
        for (int k = 0; k < KC_; k++) {
            dst[(2*k    )*A_] = __uint_as_float((unsigned)(acc2[k] & 0xffffffffu));
            dst[(2*k + 1)*A_] = __uint_as_float((unsigned)(acc2[k] >> 32));
        }
    }
}

// =============== stage 2: finalize q + reduce S -> bf16 images ===============
__global__ __launch_bounds__(128) void kstage2() {
    int b = blockIdx.x;
    int a = threadIdx.x;

    float qa = g_qp[(b*4+0)*A_ + a] + g_qp[(b*4+1)*A_ + a]
             + g_qp[(b*4+2)*A_ + a] + g_qp[(b*4+3)*A_ + a];
    g_q[b*A_ + a] = ftanh(qa);

    const float* part = &g_Sp[(size_t)(b*NCS)*J_*A_ + a];
    #pragma unroll 1
    for (int j8 = 0; j8 < 8; j8++) {
        float x[8];
        #pragma unroll
        for (int i = 0; i < 8; i++) {
            int j = j8*8 + i;
            float s = 0.0f;
            if (j < J_) {
                #pragma unroll
                for (int ch = 0; ch < NCS; ch++)
                    s += part[((size_t)ch*J_ + j)*A_];
            }
            x[i] = s;
        }
        uint4 hi, lo;
        split8(x, hi, lo);
        *reinterpret_cast<uint4*>(&gSimg[0][b][a*64 + j8*8]) = hi;
        *reinterpret_cast<uint4*>(&gSimg[1][b][a*64 + j8*8]) = lo;
    }
}

// -------- kernel 3 (hot): pure mma pipeline (stage -> compute -> sync) --------
#define SROW   144
#define TILE_B (128*SROW)               // 18432
#define OFF_A(buf,part) ((uint32_t)(((buf)*2+(part))*TILE_B))
#define OFF_B(buf,part) ((uint32_t)(73728u + ((buf)*2+(part))*TILE_B))
#define OFF_LT 147456u                  // ltanh: 128 rows x 66 half2 (33792 B)
#define OFF_EP 181248u
#define OFF_Q  183296u
#define OFF_WV 183808u
#define SMEM_DYN 184320

__global__ __launch_bounds__(256) void kmain(const float* __restrict__ Wv) {
    extern __shared__ __align__(16) char sm[];
    uint32_t smu = (uint32_t)__cvta_generic_to_shared(sm);

    int tt  = blockIdx.x;
    int b   = blockIdx.y;
    int t0  = tt * 128;
    int tid = threadIdx.x;
    int lane = tid & 31;
    int wid  = tid >> 5;
    int wr   = wid >> 2;
    int wc   = wid & 3;
    int grp  = lane >> 2;
    int tig  = lane & 3;
    int oct  = lane >> 3;
    int orow = lane & 7;

    float*   sq    = reinterpret_cast<float*>(sm + OFF_Q);
    float*   sWv   = reinterpret_cast<float*>(sm + OFF_WV);
    float*   epart = reinterpret_cast<float*>(sm + OFF_EP);
    __half2* lth   = reinterpret_cast<__half2*>(sm + OFF_LT);

    if (tid < 128) { sq[tid] = g_q[b*A_ + tid]; sWv[tid] = Wv[tid]; }

    uint32_t aoff = (uint32_t)((wr*64 + (oct & 1)*8 + orow)*SROW + (oct >> 1)*16);
    uint32_t boff = (uint32_t)((wc*32 + (oct >> 1)*8 + orow)*SROW + (oct & 1)*16);

    // prologue: stage step 0 (loc: Wconv^T -> A0, S^T -> B0)
    #pragma unroll
    for (int part = 0; part < 2; part++)
        #pragma unroll
        for (int r = 0; r < 4; r++) {
            int i = tid + r*256;
            int row = i >> 3, cc = i & 7;
            uint32_t doff = (uint32_t)(row*SROW + cc*16);
            CP16(smu + OFF_A(0, part) + doff, (const char*)&gCimg[part][tt][i*8]);
            CP16(smu + OFF_B(0, part) + doff, (const char*)&gSimg[part][b][i*8]);
        }
    CP_COMMIT();
    CP_WAIT0();
    __syncthreads();

    float acc[4][4][4];
    #pragma unroll
    for (int mt = 0; mt < 4; mt++)
        #pragma unroll
        for (int nt = 0; nt < 4; nt++)
            #pragma unroll
            for (int f = 0; f < 4; f++) acc[mt][nt][f] = 0.f;

    auto compute_chunk = [&](int pb) {
        uint32_t aH = smu + OFF_A(pb, 0) + aoff;
        uint32_t aL = smu + OFF_A(pb, 1) + aoff;
        uint32_t bHa = smu + OFF_B(pb, 0) + boff;
        uint32_t bLa = smu + OFF_B(pb, 1) + boff;
        #pragma unroll
        for (int kk = 0; kk < 4; kk++) {
            uint32_t Ah[4][4], Al[4][4];
            #pragma unroll
            for (int mt = 0; mt < 4; mt++) {
                uint32_t ad = aH + (uint32_t)(mt*16*SROW + kk*32);
                LDSM4(Ah[mt], ad);
                LDSM4(Al[mt], ad + (aL - aH));
            }
            uint32_t Bh[4][2], Bl[4][2];
            #pragma unroll
            for (int ntp = 0; ntp < 2; ntp++) {
                uint32_t bd = bHa + (uint32_t)(ntp*16*SROW + kk*32);
                uint32_t r4[4];
                LDSM4(r4, bd);
                Bh[2*ntp][0] = r4[0]; Bh[2*ntp][1] = r4[1];
                Bh[2*ntp+1][0] = r4[2]; Bh[2*ntp+1][1] = r4[3];
                LDSM4(r4, bd + (bLa - bHa));
                Bl[2*ntp][0] = r4[0]; Bl[2*ntp][1] = r4[1];
                Bl[2*ntp+1][0] = r4[2]; Bl[2*ntp+1][1] = r4[3];
            }
            #pragma unroll
            for (int nt = 0; nt < 4; nt++)
                #pragma unroll
                for (int mt = 0; mt < 4; mt++) {
                    mma4(acc[mt][nt], Ah[mt], Bh[nt][0], Bh[nt][1]);
                    mma4(acc[mt][nt], Al[mt], Bh[nt][0], Bh[nt][1]);
                    mma4(acc[mt][nt], Ah[mt], Bl[nt][0], Bl[nt][1]);
                }
        }
    };

    #pragma unroll 1
    for (int s = 0; s < 9; s++) {
        int pb = s & 1;
        int nb = (s + 1) & 1;
        if (s < 8) {
            // stage v-chunk s: A from gVimg, B from gBimg
            #pragma unroll
            for (int part = 0; part < 2; part++)
                #pragma unroll
                for (int r = 0; r < 4; r++) {
                    int i = tid + r*256;
                    int row = i >> 3, cc = i & 7;
                    uint32_t doff = (uint32_t)(row*SROW + cc*16);
                    CP16(smu + OFF_A(nb, part) + doff,
                         (const char*)&gVimg[part][(((size_t)b*T_ + t0 + row)*8 + s)*64 + cc*8]);
                    CP16(smu + OFF_B(nb, part) + doff,
                         (const char*)&gBimg[part][s][i*8]);
                }
            CP_COMMIT();
        }

        compute_chunk(pb);

        if (s == 0) {
            #pragma unroll
            for (int mt = 0; mt < 4; mt++)
                #pragma unroll
                for (int nt = 0; nt < 4; nt++)
                    #pragma unroll
                    for (int h = 0; h < 2; h++) {
                        int row = wr*64 + mt*16 + grp + h*8;
                        lth[row*66 + wc*16 + nt*4 + tig] =
                            __floats2half2_rn(ftanh(acc[mt][nt][h*2]),
                                              ftanh(acc[mt][nt][h*2+1]));
                    }
            #pragma unroll
            for (int mt = 0; mt < 4; mt++)
                #pragma unroll
                for (int nt = 0; nt < 4; nt++)
                    #pragma unroll
                    for (int f = 0; f < 4; f++) acc[mt][nt][f] = 0.f;
        }

        if (s < 8) CP_WAIT0();
        __syncthreads();
    }

    // ---- epilogue ----
    float qc[8], wv[8];
    #pragma unroll
    for (int nt = 0; nt < 4; nt++) {
        int c0 = wc*32 + nt*8 + 2*tig;
        qc[nt*2]   = sq[c0];     qc[nt*2+1] = sq[c0+1];
        wv[nt*2]   = sWv[c0];    wv[nt*2+1] = sWv[c0+1];
    }

    #pragma unroll
    for (int mt = 0; mt < 4; mt++) {
        #pragma unroll
        for (int h = 0; h < 2; h++) {
            int row = wr*64 + mt*16 + grp + h*8;
            int t = t0 + row;
            float pe = 0.0f;
            #pragma unroll
            for (int nt = 0; nt < 4; nt++) {
                float v0 = ftanh(acc[mt][nt][h*2 + 0]);
                float v1 = ftanh(acc[mt][nt][h*2 + 1]);
                float2 lt = __half22float2(lth[row*66 + wc*16 + nt*4 + tig]);
                int c0 = wc*32 + nt*8 + 2*tig;
                __half2 hv = __floats2half2_rn(v0, v1);
                *reinterpret_cast<__half2*>(&g_vh[((size_t)b*T_ + t)*A_ + c0]) = hv;
                pe += ftanh(qc[nt*2]   + v0 + lt.x) * wv[nt*2];
                pe += ftanh(qc[nt*2+1] + v1 + lt.y) * wv[nt*2+1];
            }
            pe += __shfl_xor_sync(0xffffffffu, pe, 1);
            pe += __shfl_xor_sync(0xffffffffu, pe, 2);
            if (tig == 0) epart[row*4 + wc] = pe;
        }
    }
    __syncthreads();
    if (tid < 128) {
        float e = epart[tid*4+0] + epart[tid*4+1] + epart[tid*4+2] + epart[tid*4+3];
        g_e[b*T_ + t0 + tid] = e;
    }
}

// ------- kernel 4: softmax over T + context (1024 thr, 16 t-groups) -------
__global__ __launch_bounds__(1024) void kctx(float* __restrict__ out) {
    int b = blockIdx.x;
    int tid = threadIdx.x;
    __shared__ float p[T_];
    __shared__ float red[32];
    __shared__ float cpart[16][A_];

    float e = g_e[b*T_ + tid];
    float m = e;
    #pragma unroll
    for (int o = 16; o; o >>= 1) m = fmaxf(m, __shfl_xor_sync(0xffffffffu, m, o));
    if ((tid & 31) == 0) red[tid >> 5] = m;
    __syncthreads();
    if (tid < 32) {
        float mm = red[tid];
        #pragma unroll
        for (int o = 16; o; o >>= 1) mm = fmaxf(mm, __shfl_xor_sync(0xffffffffu, mm, o));
        if (tid == 0) red[0] = mm;
    }
    __syncthreads();
    m = red[0];
    __syncthreads();

    float x = __expf(e - m);
    float s = x;
    #pragma unroll
    for (int o = 16; o; o >>= 1) s += __shfl_xor_sync(0xffffffffu, s, o);
    if ((tid & 31) == 0) red[tid >> 5] = s;
    __syncthreads();
    if (tid < 32) {
        float ss = red[tid];
        #pragma unroll
        for (int o = 16; o; o >>= 1) ss += __shfl_xor_sync(0xffffffffu, ss, o);
        if (tid == 0) red[0] = ss;
    }
    __syncthreads();
    float inv = 1.0f / red[0];

    float pv = x * inv;
    p[tid] = pv;
    out[B_*A_ + b*T_ + tid] = pv;
    __syncthreads();

    int g  = tid >> 6;
    int a2 = tid & 63;
    const __half2* vp = reinterpret_cast<const __half2*>(g_vh)
                        + ((size_t)b*T_ + (size_t)g*64)*64 + a2;
    float accx = 0.0f, accy = 0.0f;
    #pragma unroll 8
    for (int t = 0; t < 64; t++) {
        float2 vv = __half22float2(vp[(size_t)t*64]);
        float pt = p[g*64 + t];
        accx = fmaf(pt, vv.x, accx);
        accy = fmaf(pt, vv.y, accy);
    }
    cpart[g][2*a2]     = accx;
    cpart[g][2*a2 + 1] = accy;
    __syncthreads();
    if (tid < A_) {
        float c = 0.0f;
        #pragma unroll
        for (int gg = 0; gg < 16; gg++) c += cpart[gg][tid];
        out[b*A_ + tid] = c;
    }
}

// ---------------- launcher ----------------
extern "C" void kernel_launch(void* const* d_in, const int* in_sizes, int n_in,
                              void* d_out, int out_size) {
    const float* query = (const float*)d_in[0];
    const float* value = (const float*)d_in[1];
    const float* awcat = (const float*)d_in[2];
    const float* Wq    = (const float*)d_in[3];
    const float* Wm    = (const float*)d_in[4];
    const float* Wv    = (const float*)d_in[5];
    const float* Wconv = (const float*)d_in[6];
    const float* Wloc  = (const float*)d_in[7];
    float* out = (float*)d_out;

    static bool attr_set = false;
    if (!attr_set) {
        cudaFuncSetAttribute(kmain, cudaFuncAttributeMaxDynamicSharedMemorySize, SMEM_DYN);
        attr_set = true;
    }

    kstage1<<< S1_TOT, 128 >>>(value, query, Wq, Wm, Wconv, awcat, Wloc);
    kstage2<<< B_, 128 >>>();
    kmain  <<< dim3(NTT, B_), 256, SMEM_DYN >>>(Wv);
    kctx   <<< B_, 1024 >>>(out);
}

// round 15
// speedup vs baseline: 1.4032x; 1.4032x over previous
#include <cuda_runtime.h>
#include <cuda_fp16.h>
#include <cuda_bf16.h>
#include <cstdint>

#define B_  64
#define T_  1024
#define A_  128
#define F_  1024
#define KC_ 31
#define DQ_ 1024
#define DV_ 512
#define J_  62
#define NCS 8           // kS t-chunks
#define TCS 128         // t per chunk
#define NTT 8           // t-tiles of 128
#define NCH 8           // k-chunks of 64
#define CHK 8192        // elems per bf16 image chunk (128 x 64)

// ---- scratch (device globals) ----
__device__ __half g_vh[B_*T_*A_];
__device__ float g_q [B_*A_];
__device__ float g_qp[256*A_];
__device__ float g_e [B_*T_];
__device__ float g_Sp[B_*NCS*J_*A_];
__device__ __align__(16) __nv_bfloat16 gBimg[2][NCH][CHK];  // Wm^T   (row=a)
__device__ __align__(16) __nv_bfloat16 gCimg[2][NTT][CHK];  // Wconv^T(row=t_local)
__device__ __align__(16) __nv_bfloat16 gSimg[2][B_ ][CHK];  // S^T    (row=a)

__device__ __forceinline__ float ftanh(float x) {
    float e = __expf(2.0f * x);
    return 1.0f - __fdividef(2.0f, e + 1.0f);
}

__device__ __forceinline__ void split8(const float* x, uint4& hi, uint4& lo) {
    unsigned hw[4], lw[4];
    #pragma unroll
    for (int p = 0; p < 4; p++) {
        __nv_bfloat162 h = __floats2bfloat162_rn(x[2*p], x[2*p+1]);
        float r0 = x[2*p]   - __low2float(h);
        float r1 = x[2*p+1] - __high2float(h);
        __nv_bfloat162 l = __floats2bfloat162_rn(r0, r1);
        hw[p] = *reinterpret_cast<unsigned*>(&h);
        lw[p] = *reinterpret_cast<unsigned*>(&l);
    }
    hi = make_uint4(hw[0], hw[1], hw[2], hw[3]);
    lo = make_uint4(lw[0], lw[1], lw[2], lw[3]);
}

#define CP16(dst_u32, src_ptr) \
    asm volatile("cp.async.ca.shared.global [%0], [%1], 16;" \
                 :: "r"(dst_u32), "l"(src_ptr) : "memory")
#define CP_COMMIT() asm volatile("cp.async.commit_group;" ::: "memory")
#define CP_WAIT0()  asm volatile("cp.async.wait_group 0;" ::: "memory")

#define LDSM4(r, addr) \
    asm volatile("ldmatrix.sync.aligned.m8n8.x4.shared.b16 {%0,%1,%2,%3}, [%4];" \
        : "=r"((r)[0]), "=r"((r)[1]), "=r"((r)[2]), "=r"((r)[3]) : "r"(addr))

__device__ __forceinline__ void mma4(float* c, const uint32_t* a,
                                     uint32_t b0, uint32_t b1) {
    asm volatile(
        "mma.sync.aligned.m16n8k16.row.col.f32.bf16.bf16.f32 "
        "{%0,%1,%2,%3},{%4,%5,%6,%7},{%8,%9},{%0,%1,%2,%3};"
        : "+f"(c[0]), "+f"(c[1]), "+f"(c[2]), "+f"(c[3])
        : "r"(a[0]), "r"(a[1]), "r"(a[2]), "r"(a[3]), "r"(b0), "r"(b1));
}

// =============== stage 1: kq-partials | prepB | prepC | kS (fused) ===============
#define S1_KQ   256
#define S1_PB   (S1_KQ + NCH)
#define S1_PC   (S1_PB + NTT)
#define S1_TOT  (S1_PC + B_*NCS)

__global__ __launch_bounds__(128) void kstage1(const float* __restrict__ query,
                                               const float* __restrict__ Wq,
                                               const float* __restrict__ Wm,
                                               const float* __restrict__ Wconv,
                                               const float* __restrict__ aw,
                                               const float* __restrict__ Wloc) {
    int blk = blockIdx.x;
    int tid = threadIdx.x;

    if (blk < S1_KQ) {
        int b = blk >> 2, qq = blk & 3;
        __shared__ float qs[256];
        qs[tid]       = query[b*DQ_ + qq*256 + tid];
        qs[tid + 128] = query[b*DQ_ + qq*256 + 128 + tid];
        __syncthreads();
        float acc = 0.0f;
        #pragma unroll 8
        for (int d = 0; d < 256; d++)
            acc = fmaf(qs[d], Wq[(size_t)(qq*256 + d)*A_ + tid], acc);
        g_qp[blk*A_ + tid] = acc;
    } else if (blk < S1_PB) {
        int c = blk - S1_KQ;
        #pragma unroll 1
        for (int k8 = 0; k8 < 8; k8++) {
            float x[8];
            #pragma unroll
            for (int i = 0; i < 8; i++)
                x[i] = Wm[(size_t)(c*64 + k8*8 + i)*A_ + tid];
            uint4 hi, lo;
            split8(x, hi, lo);
            *reinterpret_cast<uint4*>(&gBimg[0][c][tid*64 + k8*8]) = hi;
            *reinterpret_cast<uint4*>(&gBimg[1][c][tid*64 + k8*8]) = lo;
        }
    } else if (blk < S1_PC) {
        int tt = blk - S1_PB;
        #pragma unroll 1
        for (int k8 = 0; k8 < 8; k8++) {
            float x[8];
            #pragma unroll
            for (int i = 0; i < 8; i++) {
                int j = k8*8 + i;
                x[i] = (j < J_) ? Wconv[(size_t)j*F_ + tt*128 + tid] : 0.0f;
            }
            uint4 hi, lo;
            split8(x, hi, lo);
            *reinterpret_cast<uint4*>(&gCimg[0][tt][tid*64 + k8*8]) = hi;
            *reinterpret_cast<uint4*>(&gCimg[1][tt][tid*64 + k8*8]) = lo;
        }
    } else {
        int i  = blk - S1_PC;
        int b  = i >> 3;
        int ch = i & 7;
        int t0 = ch * TCS;

        __shared__ float2 awm2[TCS + KC_ - 1];
        for (int idx = tid; idx < TCS + KC_ - 1; idx += 128) {
            int t = t0 + idx - 15;
            float2 v = make_float2(0.0f, 0.0f);
            if (t >= 0 && t < T_) {
                v.x = aw[(b*T_ + t)*2 + 0];
                v.y = aw[(b*T_ + t)*2 + 1];
            }
            awm2[idx] = v;
        }
        __syncthreads();

        unsigned long long acc2[KC_];
        #pragma unroll
        for (int k = 0; k < KC_; k++) acc2[k] = 0ull;

        #pragma unroll 1
        for (int tl = 0; tl < TCS; tl++) {
            float w = Wloc[(size_t)(t0 + tl)*A_ + tid];
            unsigned long long wd;
            asm("mov.b64 %0, {%1,%1};" : "=l"(wd) : "f"(w));
            #pragma unroll
            for (int k = 0; k < KC_; k++) {
                unsigned long long bv = *reinterpret_cast<const unsigned long long*>(&awm2[tl + k]);
                asm("fma.rn.f32x2 %0, %1, %2, %0;" : "+l"(acc2[k]) : "l"(wd), "l"(bv));
            }
        }
        float* dst = &g_Sp[((size_t)(b*NCS + ch)*J_)*A_ + tid];
        #pragma unroll
        for (int k = 0; k < KC_; k++) {
            dst[(2*k    )*A_] = __uint_as_float((unsigned)(acc2[k] & 0xffffffffu));
            dst[(2*k + 1)*A_] = __uint_as_float((unsigned)(acc2[k] >> 32));
        }
    }
}

// =============== stage 2: finalize q + reduce S -> bf16 images ===============
__global__ __launch_bounds__(128) void kstage2() {
    int b = blockIdx.x;
    int a = threadIdx.x;

    float qa = g_qp[(b*4+0)*A_ + a] + g_qp[(b*4+1)*A_ + a]
             + g_qp[(b*4+2)*A_ + a] + g_qp[(b*4+3)*A_ + a];
    g_q[b*A_ + a] = ftanh(qa);

    const float* part = &g_Sp[(size_t)(b*NCS)*J_*A_ + a];
    #pragma unroll 1
    for (int j8 = 0; j8 < 8; j8++) {
        float x[8];
        #pragma unroll
        for (int i = 0; i < 8; i++) {
            int j = j8*8 + i;
            float s = 0.0f;
            if (j < J_) {
                #pragma unroll
                for (int ch = 0; ch < NCS; ch++)
                    s += part[((size_t)ch*J_ + j)*A_];
            }
            x[i] = s;
        }
        uint4 hi, lo;
        split8(x, hi, lo);
        *reinterpret_cast<uint4*>(&gSimg[0][b][a*64 + j8*8]) = hi;
        *reinterpret_cast<uint4*>(&gSimg[1][b][a*64 + j8*8]) = lo;
    }
}

// ---- kernel 3 (hot): mma.sync pipeline, register-staged value, overlapped convert ----
#define SROW   144
#define TILE_B (128*SROW)               // 18432
#define OFF_A(buf,part) ((uint32_t)(((buf)*2+(part))*TILE_B))
#define OFF_B(buf,part) ((uint32_t)(73728u + ((buf)*2+(part))*TILE_B))
#define OFF_LT 147456u                  // ltanh: 128 rows x 66 half2 (33792 B)
#define OFF_EP 181248u
#define OFF_Q  183296u
#define OFF_WV 183808u
#define SMEM_DYN 184320

__global__ __launch_bounds__(256) void kmain(const float* __restrict__ value,
                                             const float* __restrict__ Wv) {
    extern __shared__ __align__(16) char sm[];
    uint32_t smu = (uint32_t)__cvta_generic_to_shared(sm);

    int tt  = blockIdx.x;
    int b   = blockIdx.y;
    int t0  = tt * 128;
    int tid = threadIdx.x;
    int lane = tid & 31;
    int wid  = tid >> 5;
    int wr   = wid >> 2;
    int wc   = wid & 3;
    int grp  = lane >> 2;
    int tig  = lane & 3;
    int oct  = lane >> 3;
    int orow = lane & 7;

    float*   sq    = reinterpret_cast<float*>(sm + OFF_Q);
    float*   sWv   = reinterpret_cast<float*>(sm + OFF_WV);
    float*   epart = reinterpret_cast<float*>(sm + OFF_EP);
    __half2* lth   = reinterpret_cast<__half2*>(sm + OFF_LT);

    if (tid < 128) { sq[tid] = g_q[b*A_ + tid]; sWv[tid] = Wv[tid]; }

    uint32_t aoff = (uint32_t)((wr*64 + (oct & 1)*8 + orow)*SROW + (oct >> 1)*16);
    uint32_t boff = (uint32_t)((wc*32 + (oct >> 1)*8 + orow)*SROW + (oct & 1)*16);

    // value LDG mapping: row = tid>>1, k-half = tid&1 (32 floats per thread/chunk)
    int vrow = tid >> 1;
    int vkh  = tid & 1;
    const float* vbase = value + ((size_t)(b*T_ + t0) + vrow)*DV_ + vkh*32;

    // prologue: stage loc operands (Wconv^T -> A0, S^T -> B0); LDG chunk 0
    #pragma unroll
    for (int part = 0; part < 2; part++)
        #pragma unroll
        for (int r = 0; r < 4; r++) {
            int i = tid + r*256;
            int row = i >> 3, cc = i & 7;
            uint32_t doff = (uint32_t)(row*SROW + cc*16);
            CP16(smu + OFF_A(0, part) + doff, (const char*)&gCimg[part][tt][i*8]);
            CP16(smu + OFF_B(0, part) + doff, (const char*)&gSimg[part][b][i*8]);
        }
    CP_COMMIT();

    float4 vfa[8], vfb[8];
    #pragma unroll
    for (int g = 0; g < 8; g++)
        vfa[g] = *reinterpret_cast<const float4*>(vbase + g*4);

    CP_WAIT0();
    __syncthreads();

    float acc[4][4][4];
    #pragma unroll
    for (int mt = 0; mt < 4; mt++)
        #pragma unroll
        for (int nt = 0; nt < 4; nt++)
            #pragma unroll
            for (int f = 0; f < 4; f++) acc[mt][nt][f] = 0.f;

    auto compute_chunk = [&](int pb) {
        uint32_t aH = smu + OFF_A(pb, 0) + aoff;
        uint32_t aL = smu + OFF_A(pb, 1) + aoff;
        uint32_t bHa = smu + OFF_B(pb, 0) + boff;
        uint32_t bLa = smu + OFF_B(pb, 1) + boff;
        #pragma unroll
        for (int kk = 0; kk < 4; kk++) {
            uint32_t Ah[4][4], Al[4][4];
            #pragma unroll
            for (int mt = 0; mt < 4; mt++) {
                uint32_t ad = aH + (uint32_t)(mt*16*SROW + kk*32);
                LDSM4(Ah[mt], ad);
                LDSM4(Al[mt], ad + (aL - aH));
            }
            uint32_t Bh[4][2], Bl[4][2];
            #pragma unroll
            for (int ntp = 0; ntp < 2; ntp++) {
                uint32_t bd = bHa + (uint32_t)(ntp*16*SROW + kk*32);
                uint32_t r4[4];
                LDSM4(r4, bd);
                Bh[2*ntp][0] = r4[0]; Bh[2*ntp][1] = r4[1];
                Bh[2*ntp+1][0] = r4[2]; Bh[2*ntp+1][1] = r4[3];
                LDSM4(r4, bd + (bLa - bHa));
                Bl[2*ntp][0] = r4[0]; Bl[2*ntp][1] = r4[1];
                Bl[2*ntp+1][0] = r4[2]; Bl[2*ntp+1][1] = r4[3];
            }
            #pragma unroll
            for (int nt = 0; nt < 4; nt++)
                #pragma unroll
                for (int mt = 0; mt < 4; mt++) {
                    mma4(acc[mt][nt], Ah[mt], Bh[nt][0], Bh[nt][1]);
                    mma4(acc[mt][nt], Al[mt], Bh[nt][0], Bh[nt][1]);
                    mma4(acc[mt][nt], Ah[mt], Bl[nt][0], Bl[nt][1]);
                }
        }
    };

    // body: iter s computes chunk (s) from buf pb=s&1, prepares buf nb for s+1:
    //   cp.async B (Wm^T chunk s) -> B[nb]; LDG value chunk s+1 -> nxt;
    //   convert cur (value chunk s, fp32 regs) -> A[nb]   [overlaps compute across warps]
    auto body = [&](int s, float4 (&cur)[8], float4 (&nxt)[8]) {
        int pb = s & 1;
        int nb = (s + 1) & 1;
        if (s < 8) {
            #pragma unroll
            for (int part = 0; part < 2; part++)
                #pragma unroll
                for (int r = 0; r < 4; r++) {
                    int i = tid + r*256;
                    int row = i >> 3, cc = i & 7;
                    CP16(smu + OFF_B(nb, part) + (uint32_t)(row*SROW + cc*16),
                         (const char*)&gBimg[part][s][i*8]);
                }
            CP_COMMIT();
            if (s < 7) {
                const float* src = vbase + (s + 1)*64;
                #pragma unroll
                for (int g = 0; g < 8; g++)
                    nxt[g] = *reinterpret_cast<const float4*>(src + g*4);
            }
            // convert cur -> A[nb]; interleaves with other warps' MMAs
            char* dH = sm + OFF_A(nb, 0) + vrow*SROW + vkh*64;
            char* dL = sm + OFF_A(nb, 1) + vrow*SROW + vkh*64;
            #pragma unroll
            for (int g = 0; g < 4; g++) {
                float x[8];
                x[0]=cur[2*g].x;   x[1]=cur[2*g].y;   x[2]=cur[2*g].z;   x[3]=cur[2*g].w;
                x[4]=cur[2*g+1].x; x[5]=cur[2*g+1].y; x[6]=cur[2*g+1].z; x[7]=cur[2*g+1].w;
                uint4 hi, lo;
                split8(x, hi, lo);
                *reinterpret_cast<uint4*>(dH + g*16) = hi;
                *reinterpret_cast<uint4*>(dL + g*16) = lo;
            }
        }

        compute_chunk(pb);

        if (s == 0) {   // park tanh(loc), reuse accumulators for v-GEMM
            #pragma unroll
            for (int mt = 0; mt < 4; mt++)
                #pragma unroll
                for (int nt = 0; nt < 4; nt++)
                    #pragma unroll
                    for (int h = 0; h < 2; h++) {
                        int row = wr*64 + mt*16 + grp + h*8;
                        lth[row*66 + wc*16 + nt*4 + tig] =
                            __floats2half2_rn(ftanh(acc[mt][nt][h*2]),
                                              ftanh(acc[mt][nt][h*2+1]));
                    }
            #pragma unroll
            for (int mt = 0; mt < 4; mt++)
                #pragma unroll
                for (int nt = 0; nt < 4; nt++)
                    #pragma unroll
                    for (int f = 0; f < 4; f++) acc[mt][nt][f] = 0.f;
        }

        if (s < 8) CP_WAIT0();
        __syncthreads();
    };

    #pragma unroll 1
    for (int sp = 0; sp < 10; sp += 2) {
        body(sp, vfa, vfb);
        if (sp < 8) body(sp + 1, vfb, vfa);
    }

    // ---- epilogue ----
    float qc[8], wv[8];
    #pragma unroll
    for (int nt = 0; nt < 4; nt++) {
        int c0 = wc*32 + nt*8 + 2*tig;
        qc[nt*2]   = sq[c0];     qc[nt*2+1] = sq[c0+1];
        wv[nt*2]   = sWv[c0];    wv[nt*2+1] = sWv[c0+1];
    }

    #pragma unroll
    for (int mt = 0; mt < 4; mt++) {
        #pragma unroll
        for (int h = 0; h < 2; h++) {
            int row = wr*64 + mt*16 + grp + h*8;
            int t = t0 + row;
            float pe = 0.0f;
            #pragma unroll
            for (int nt = 0; nt < 4; nt++) {
                float v0 = ftanh(acc[mt][nt][h*2 + 0]);
                float v1 = ftanh(acc[mt][nt][h*2 + 1]);
                float2 lt = __half22float2(lth[row*66 + wc*16 + nt*4 + tig]);
                int c0 = wc*32 + nt*8 + 2*tig;
                __half2 hv = __floats2half2_rn(v0, v1);
                *reinterpret_cast<__half2*>(&g_vh[((size_t)b*T_ + t)*A_ + c0]) = hv;
                pe += ftanh(qc[nt*2]   + v0 + lt.x) * wv[nt*2];
                pe += ftanh(qc[nt*2+1] + v1 + lt.y) * wv[nt*2+1];
            }
            pe += __shfl_xor_sync(0xffffffffu, pe, 1);
            pe += __shfl_xor_sync(0xffffffffu, pe, 2);
            if (tig == 0) epart[row*4 + wc] = pe;
        }
    }
    __syncthreads();
    if (tid < 128) {
        float e = epart[tid*4+0] + epart[tid*4+1] + epart[tid*4+2] + epart[tid*4+3];
        g_e[b*T_ + t0 + tid] = e;
    }
}

// ------- kernel 4: softmax over T + context (1024 thr, 16 t-groups) -------
__global__ __launch_bounds__(1024) void kctx(float* __restrict__ out) {
    int b = blockIdx.x;
    int tid = threadIdx.x;
    __shared__ float p[T_];
    __shared__ float red[32];
    __shared__ float cpart[16][A_];

    float e = g_e[b*T_ + tid];
    float m = e;
    #pragma unroll
    for (int o = 16; o; o >>= 1) m = fmaxf(m, __shfl_xor_sync(0xffffffffu, m, o));
    if ((tid & 31) == 0) red[tid >> 5] = m;
    __syncthreads();
    if (tid < 32) {
        float mm = red[tid];
        #pragma unroll
        for (int o = 16; o; o >>= 1) mm = fmaxf(mm, __shfl_xor_sync(0xffffffffu, mm, o));
        if (tid == 0) red[0] = mm;
    }
    __syncthreads();
    m = red[0];
    __syncthreads();

    float x = __expf(e - m);
    float s = x;
    #pragma unroll
    for (int o = 16; o; o >>= 1) s += __shfl_xor_sync(0xffffffffu, s, o);
    if ((tid & 31) == 0) red[tid >> 5] = s;
    __syncthreads();
    if (tid < 32) {
        float ss = red[tid];
        #pragma unroll
        for (int o = 16; o; o >>= 1) ss += __shfl_xor_sync(0xffffffffu, ss, o);
        if (tid == 0) red[0] = ss;
    }
    __syncthreads();
    float inv = 1.0f / red[0];

    float pv = x * inv;
    p[tid] = pv;
    out[B_*A_ + b*T_ + tid] = pv;
    __syncthreads();

    int g  = tid >> 6;
    int a2 = tid & 63;
    const __half2* vp = reinterpret_cast<const __half2*>(g_vh)
                        + ((size_t)b*T_ + (size_t)g*64)*64 + a2;
    float accx = 0.0f, accy = 0.0f;
    #pragma unroll 8
    for (int t = 0; t < 64; t++) {
        float2 vv = __half22float2(vp[(size_t)t*64]);
        float pt = p[g*64 + t];
        accx = fmaf(pt, vv.x, accx);
        accy = fmaf(pt, vv.y, accy);
    }
    cpart[g][2*a2]     = accx;
    cpart[g][2*a2 + 1] = accy;
    __syncthreads();
    if (tid < A_) {
        float c = 0.0f;
        #pragma unroll
        for (int gg = 0; gg < 16; gg++) c += cpart[gg][tid];
        out[b*A_ + tid] = c;
    }
}

// ---------------- launcher ----------------
extern "C" void kernel_launch(void* const* d_in, const int* in_sizes, int n_in,
                              void* d_out, int out_size) {
    const float* query = (const float*)d_in[0];
    const float* value = (const float*)d_in[1];
    const float* awcat = (const float*)d_in[2];
    const float* Wq    = (const float*)d_in[3];
    const float* Wm    = (const float*)d_in[4];
    const float* Wv    = (const float*)d_in[5];
    const float* Wconv = (const float*)d_in[6];
    const float* Wloc  = (const float*)d_in[7];
    float* out = (float*)d_out;

    static bool attr_set = false;
    if (!attr_set) {
        cudaFuncSetAttribute(kmain, cudaFuncAttributeMaxDynamicSharedMemorySize, SMEM_DYN);
        attr_set = true;
    }

    kstage1<<< S1_TOT, 128 >>>(query, Wq, Wm, Wconv, awcat, Wloc);
    kstage2<<< B_, 128 >>>();
    kmain  <<< dim3(NTT, B_), 256, SMEM_DYN >>>(value, Wv);
    kctx   <<< B_, 1024 >>>(out);
}